// round 13
// baseline (speedup 1.0000x reference)
#include <cuda_runtime.h>
#include <cuda_bf16.h>
#include <cstdint>

#define N_ROWS 131072
#define DIM    256
#define KCB    1024

// full-rescue tile
#define BM 32
#define BN 128
#define BD 32
#define PAD 4

__device__ float  g_cnorm[KCB];
__device__ float  g_zn[N_ROWS];
__device__ float  g_s1[N_ROWS];
__device__ int    g_ids[N_ROWS];
__device__ int    g_lite[N_ROWS];
__device__ int    g_c1[N_ROWS];
__device__ int    g_c2[N_ROWS];
__device__ int    g_full[N_ROWS];
__device__ int    g_nlite;
__device__ int    g_nfull;
__device__ double g_loss;
__device__ __align__(16) signed char g_zq[(size_t)N_ROWS * DIM];
__device__ __align__(16) signed char g_cbq[KCB * DIM];

typedef unsigned long long u64;

#define FMA_F32X2(d, a, b, c) \
    asm("fma.rn.f32x2 %0, %1, %2, %3;" : "=l"(d) : "l"(a), "l"(b), "l"(c))
#define DUP_F32X2(d, x) \
    asm("mov.b64 %0, {%1, %1};" : "=l"(d) : "r"(x))
__device__ __forceinline__ float lo32(u64 v) { return __uint_as_float((unsigned)(v & 0xFFFFFFFFu)); }
__device__ __forceinline__ float hi32(u64 v) { return __uint_as_float((unsigned)(v >> 32)); }

// ---------------------------------------------------------------------------
// Norms (bit-exact XLA order) + int8 quantization of z (per-row) and codebook
// ---------------------------------------------------------------------------
__global__ void norms_kernel(const float* __restrict__ z, const float* __restrict__ cb) {
    int gtid = blockIdx.x * blockDim.x + threadIdx.x;
    int warp = gtid >> 5;
    int lane = threadIdx.x & 31;
    if (gtid == 0) { g_loss = 0.0; g_nlite = 0; g_nfull = 0; }
    if (warp < N_ROWS) {
        const float* row = z + (size_t)warp * DIM;
        float v[8];
        float s = 0.f, m = 0.f;
#pragma unroll
        for (int i = 0; i < 8; ++i) {
            v[i] = row[lane + i * 32];
            s = __fadd_rn(s, __fmul_rn(v[i], v[i]));   // exact reference chain
            m = fmaxf(m, fabsf(v[i]));
        }
#pragma unroll
        for (int o = 16; o > 0; o >>= 1)
            s = __fadd_rn(s, __shfl_down_sync(0xFFFFFFFFu, s, o));
#pragma unroll
        for (int o = 16; o > 0; o >>= 1)
            m = fmaxf(m, __shfl_xor_sync(0xFFFFFFFFu, m, o));
        float s1 = (m > 0.f) ? (m / 127.f) : 1.f;
        float inv = 1.f / s1;
#pragma unroll
        for (int i = 0; i < 8; ++i) {
            int q = __float2int_rn(v[i] * inv);
            g_zq[(size_t)warp * DIM + lane + i * 32] = (signed char)q;
        }
        if (lane == 0) { g_zn[warp] = s; g_s1[warp] = s1; }
    }
    if (warp < KCB) {
        const float* row = cb + (size_t)warp * DIM;
        float s = 0.f;
#pragma unroll
        for (int i = 0; i < 8; ++i) {
            float v = row[lane + i * 32];
            s = __fadd_rn(s, __fmul_rn(v, v));
            int q = __float2int_rn(v * 32512.f);
            g_cbq[warp * DIM + lane + i * 32] = (signed char)q;
        }
#pragma unroll
        for (int o = 16; o > 0; o >>= 1)
            s = __fadd_rn(s, __shfl_down_sync(0xFFFFFFFFu, s, o));
        if (lane == 0) g_cnorm[warp] = s;
    }
}

// ---------------------------------------------------------------------------
// Screening: mma.m16n8k32 s8 -> s32 (exact int dots), top-3 per row,
// per-row delta; lite (2-candidate) vs full rescue routing.
// CTA = 128 threads (4 warps), 128 rows; codebook chunks of 64 codes,
// cp.async double-buffered.
// ---------------------------------------------------------------------------
#define LDZB  272                     // int8 row stride (17 x 16B)
#define S_ZQ  0                       // z int8 [128][272]    34816
#define S_CB0 34816                   // cb int8 [64][272]    17408
#define S_CB1 52224                   //                      17408
#define S_CN  69632                   // cnorm f32 [1024]      4096
#define S_S1  73728                   // s1 f32 [128]           512
#define S_TOT 74240

#define LDSM_X4(r0, r1, r2, r3, addr) \
    asm volatile("ldmatrix.sync.aligned.m8n8.x4.shared.b16 {%0,%1,%2,%3}, [%4];" \
                 : "=r"(r0), "=r"(r1), "=r"(r2), "=r"(r3) : "r"(addr))
#define LDSM_X2(r0, r1, addr) \
    asm volatile("ldmatrix.sync.aligned.m8n8.x2.shared.b16 {%0,%1}, [%2];" \
                 : "=r"(r0), "=r"(r1) : "r"(addr))
#define MMA_S8(c, a, b) \
    asm volatile("mma.sync.aligned.m16n8k32.row.col.s32.s8.s8.s32 " \
                 "{%0,%1,%2,%3}, {%4,%5,%6,%7}, {%8,%9}, {%0,%1,%2,%3};" \
                 : "+r"((c)[0]), "+r"((c)[1]), "+r"((c)[2]), "+r"((c)[3]) \
                 : "r"((a)[0]), "r"((a)[1]), "r"((a)[2]), "r"((a)[3]), \
                   "r"((b)[0]), "r"((b)[1]))
#define CP_ASYNC16(smem_addr, gptr) \
    asm volatile("cp.async.cg.shared.global [%0], [%1], 16;" \
                 :: "r"(smem_addr), "l"(gptr) : "memory")
#define CP_COMMIT() asm volatile("cp.async.commit_group;" ::: "memory")

__device__ __forceinline__ uint32_t smem_u32(const void* p) {
    uint32_t a;
    asm("{ .reg .u64 t; cvta.to.shared.u64 t, %1; cvt.u32.u64 %0, t; }" : "=r"(a) : "l"(p));
    return a;
}

__global__ void __launch_bounds__(128)
screen_kernel() {
    extern __shared__ char smem[];
    float* cn_s = (float*)(smem + S_CN);
    float* s1_s = (float*)(smem + S_S1);

    const int tid = threadIdx.x, lane = tid & 31;
    const int w = tid >> 5;
    const int blockRow = blockIdx.x * 128;
    const int warpRow = w * 32;

    const uint32_t sb = smem_u32(smem);
    const uint32_t cbBuf[2] = {sb + S_CB0, sb + S_CB1};

    for (int t = tid; t < KCB; t += 128) cn_s[t] = g_cnorm[t];
    if (tid < 128) s1_s[tid] = g_s1[blockRow + tid];

    // stage z int8 tile [128 x 256] -> smem (stride 272)
    for (int idx = tid; idx < 128 * 16; idx += 128) {
        int row = idx >> 4, u = idx & 15;
        uint4 v = *(const uint4*)&g_zq[(size_t)(blockRow + row) * DIM + u * 16];
        *(uint4*)(smem + S_ZQ + row * LDZB + u * 16) = v;
    }

    auto stage = [&](int c, uint32_t buf) {
#pragma unroll
        for (int i = 0; i < 8; ++i) {
            int idx = tid + i * 128;          // 0..1023
            int row = idx >> 4, u = idx & 15;
            const signed char* src = &g_cbq[(c * 64 + row) * DIM + u * 16];
            CP_ASYNC16(buf + (uint32_t)(row * LDZB + u * 16), src);
        }
        CP_COMMIT();
    };

    // ldmatrix lane addressing (byte-identical to validated bf16 pattern)
    const int a_row = (lane & 7) + ((lane >> 3) & 1) * 8;
    const int a_cb  = ((lane >> 4) & 1) * 16;           // byte offset
    uint32_t addrA0 = sb + S_ZQ + (warpRow + a_row) * LDZB + a_cb;
    uint32_t addrA1 = sb + S_ZQ + (warpRow + 16 + a_row) * LDZB + a_cb;
    const int b_code = lane & 7;
    const int b_kb   = ((lane >> 3) & 1) * 16;          // byte offset

    // 4 row-slots: s = mt*2+hi -> row warpRow + mt*16 + (lane>>2) + hi*8
    float b1[4], b2[4], b3[4];
    int   i1[4], i2[4], i3[4];
#pragma unroll
    for (int s = 0; s < 4; ++s) {
        b1[s] = b2[s] = b3[s] = 3.4e38f;
        i1[s] = i2[s] = i3[s] = 0;
    }
    float sc2[4];  // 2*s1/32512 per slot
#pragma unroll
    for (int s = 0; s < 4; ++s) {
        int r = warpRow + (s >> 1) * 16 + (lane >> 2) + (s & 1) * 8;
        sc2[s] = 2.f * s1_s[r] / 32512.f;
    }

    stage(0, cbBuf[0]);

#pragma unroll 1
    for (int c = 0; c < 16; ++c) {
        if (c < 15) { stage(c + 1, cbBuf[(c + 1) & 1]);
                      asm volatile("cp.async.wait_group 1;" ::: "memory"); }
        else        { asm volatile("cp.async.wait_group 0;" ::: "memory"); }
        __syncthreads();
        const uint32_t cbb = cbBuf[c & 1];

        int acc[2][8][4];
#pragma unroll
        for (int mt = 0; mt < 2; ++mt)
#pragma unroll
            for (int nt = 0; nt < 8; ++nt)
#pragma unroll
                for (int e = 0; e < 4; ++e) acc[mt][nt][e] = 0;

#pragma unroll
        for (int ks = 0; ks < 8; ++ks) {      // 256 bytes / 32 per MMA
            uint32_t a0[4], a1[4];
            LDSM_X4(a0[0], a0[1], a0[2], a0[3], addrA0 + ks * 32);
            LDSM_X4(a1[0], a1[1], a1[2], a1[3], addrA1 + ks * 32);
            uint32_t bf[8][2];
#pragma unroll
            for (int nt = 0; nt < 8; ++nt) {
                uint32_t ab = cbb + (nt * 8 + b_code) * LDZB + b_kb + ks * 32;
                LDSM_X2(bf[nt][0], bf[nt][1], ab);
            }
#pragma unroll
            for (int nt = 0; nt < 8; ++nt) {
                MMA_S8(acc[0][nt], a0, bf[nt]);
                MMA_S8(acc[1][nt], a1, bf[nt]);
            }
        }

        // epilogue: approx score v = cn - (2*s1/32512)*dot_int ; top-3 insert
        const int kq = 2 * (lane & 3);
#pragma unroll
        for (int nt = 0; nt < 8; ++nt) {
            int k0 = c * 64 + nt * 8 + kq;
            float cn0 = cn_s[k0], cn1 = cn_s[k0 + 1];
#pragma unroll
            for (int mt = 0; mt < 2; ++mt) {
#pragma unroll
                for (int hi = 0; hi < 2; ++hi) {
                    int s = mt * 2 + hi;
                    float d0 = __int2float_rn(acc[mt][nt][hi * 2 + 0]);
                    float d1 = __int2float_rn(acc[mt][nt][hi * 2 + 1]);
                    float v0 = fmaf(-sc2[s], d0, cn0);
                    float v1 = fmaf(-sc2[s], d1, cn1);
                    if (v0 < b1[s]) { b3[s]=b2[s]; i3[s]=i2[s]; b2[s]=b1[s]; i2[s]=i1[s]; b1[s]=v0; i1[s]=k0; }
                    else if (v0 < b2[s]) { b3[s]=b2[s]; i3[s]=i2[s]; b2[s]=v0; i2[s]=k0; }
                    else if (v0 < b3[s]) { b3[s]=v0; i3[s]=k0; }
                    if (v1 < b1[s]) { b3[s]=b2[s]; i3[s]=i2[s]; b2[s]=b1[s]; i2[s]=i1[s]; b1[s]=v1; i1[s]=k0+1; }
                    else if (v1 < b2[s]) { b3[s]=b2[s]; i3[s]=i2[s]; b2[s]=v1; i2[s]=k0+1; }
                    else if (v1 < b3[s]) { b3[s]=v1; i3[s]=k0+1; }
                }
            }
        }
        __syncthreads();
    }

    // quad merge of top-3 (lanes 4r..4r+3 share the same rows)
#pragma unroll
    for (int off = 1; off <= 2; off <<= 1) {
#pragma unroll
        for (int s = 0; s < 4; ++s) {
            float o1 = __shfl_xor_sync(0xFFFFFFFFu, b1[s], off);
            float o2 = __shfl_xor_sync(0xFFFFFFFFu, b2[s], off);
            float o3 = __shfl_xor_sync(0xFFFFFFFFu, b3[s], off);
            int   j1 = __shfl_xor_sync(0xFFFFFFFFu, i1[s], off);
            int   j2 = __shfl_xor_sync(0xFFFFFFFFu, i2[s], off);
            int   j3 = __shfl_xor_sync(0xFFFFFFFFu, i3[s], off);
#pragma unroll
            for (int t = 0; t < 3; ++t) {
                float ov = (t == 0) ? o1 : (t == 1) ? o2 : o3;
                int   oj = (t == 0) ? j1 : (t == 1) ? j2 : j3;
                if (ov < b1[s]) { b3[s]=b2[s]; i3[s]=i2[s]; b2[s]=b1[s]; i2[s]=i1[s]; b1[s]=ov; i1[s]=oj; }
                else if (ov < b2[s]) { b3[s]=b2[s]; i3[s]=i2[s]; b2[s]=ov; i2[s]=oj; }
                else if (ov < b3[s]) { b3[s]=ov; i3[s]=oj; }
            }
        }
    }

    if ((lane & 3) == 0) {
#pragma unroll
        for (int s = 0; s < 4; ++s) {
            int row = blockRow + warpRow + (s >> 1) * 16 + (lane >> 2) + (s & 1) * 8;
            g_ids[row] = i1[s];
            float s1v = sc2[s] * 32512.f * 0.5f;
            float del = 12.f * sqrtf(2.16e-4f * s1v * s1v + 4e-8f);
            if (b2[s] - b1[s] < del) {
                if (b3[s] - b1[s] < del) {
                    int p = atomicAdd(&g_nfull, 1);
                    g_full[p] = row;
                } else {
                    int p = atomicAdd(&g_nlite, 1);
                    g_lite[p] = row; g_c1[p] = i1[s]; g_c2[p] = i2[s];
                }
            }
        }
    }
}

// ---------------------------------------------------------------------------
// Lite rescue: exact quantized 2-candidate compare (bit-exact serial chains)
// ---------------------------------------------------------------------------
__global__ void __launch_bounds__(256)
lite_kernel(const float* __restrict__ z, const float* __restrict__ cb) {
    __shared__ float buf[8][3][DIM];
    const int lw = threadIdx.x >> 5, lane = threadIdx.x & 31;
    const int nwarps = gridDim.x * 8;
    const int nl = g_nlite;
    for (int wi = blockIdx.x * 8 + lw; wi < nl; wi += nwarps) {
        int row = g_lite[wi], c1 = g_c1[wi], c2 = g_c2[wi];
        {
            const float4* pz = (const float4*)(z + (size_t)row * DIM);
            const float4* p1 = (const float4*)(cb + (size_t)c1 * DIM);
            const float4* p2 = (const float4*)(cb + (size_t)c2 * DIM);
            float4* bz = (float4*)buf[lw][0];
            float4* b1 = (float4*)buf[lw][1];
            float4* b2 = (float4*)buf[lw][2];
            bz[lane] = pz[lane]; bz[lane + 32] = pz[lane + 32];
            b1[lane] = p1[lane]; b1[lane + 32] = p1[lane + 32];
            b2[lane] = p2[lane]; b2[lane + 32] = p2[lane + 32];
        }
        __syncwarp();
        if (lane == 0) {
            float e1 = 0.f, e2 = 0.f;
#pragma unroll 16
            for (int d = 0; d < DIM; ++d) {
                float zv = buf[lw][0][d];
                e1 = fmaf(zv, buf[lw][1][d], e1);
                e2 = fmaf(zv, buf[lw][2][d], e2);
            }
            float zn = g_zn[row];
            float v1 = __fadd_rn(fmaf(-2.f, e1, zn), g_cnorm[c1]);
            float v2 = __fadd_rn(fmaf(-2.f, e2, zn), g_cnorm[c2]);
            int id = c1;
            if (v2 < v1 || (v2 == v1 && c2 < c1)) id = c2;
            g_ids[row] = id;
        }
        __syncwarp();
    }
}

// ---------------------------------------------------------------------------
// Full rescue (bit-exact FFMA2), BM=32 rows/block — validated kernel
// ---------------------------------------------------------------------------
__global__ void __launch_bounds__(256)
rescue_kernel(const float* __restrict__ z, const float* __restrict__ cb) {
    __shared__ __align__(16) float zs[BD][BM + PAD];
    __shared__ __align__(16) float cs[BD][BN + PAD];
    __shared__ float zn_s[BM];
    __shared__ int   ridx_s[BM];
    __shared__ float redv[BM][16];
    __shared__ int   redi[BM][16];

    const int nf = g_nfull;
    const int blockRow = blockIdx.x * BM;
    if (blockRow >= nf) return;

    const int tid = threadIdx.x;
    const int tx = tid & 15;
    const int ty = tid >> 4;

    if (tid < BM) {
        int s = blockRow + tid;
        int r = g_full[(s < nf) ? s : blockRow];
        ridx_s[tid] = r;
        zn_s[tid] = g_zn[r];
    }

    float bestv[2] = {3.4e38f, 3.4e38f};
    int   besti[2] = {0, 0};

    const int c4 = tid & 7;
    const int r0 = tid >> 3;

#pragma unroll 1
    for (int kt = 0; kt < KCB; kt += BN) {
        u64 acc[8];
#pragma unroll
        for (int j = 0; j < 8; ++j) acc[j] = 0ull;

#pragma unroll 1
        for (int dt = 0; dt < DIM; dt += BD) {
            __syncthreads();
            if (r0 < 32) {
                float4 v = *(const float4*)&z[(size_t)ridx_s[r0] * DIM + dt + c4 * 4];
                zs[c4 * 4 + 0][r0] = v.x; zs[c4 * 4 + 1][r0] = v.y;
                zs[c4 * 4 + 2][r0] = v.z; zs[c4 * 4 + 3][r0] = v.w;
            }
#pragma unroll
            for (int q = 0; q < 4; ++q) {
                int r = q * 32 + r0;
                float4 wv = *(const float4*)&cb[(size_t)(kt + r) * DIM + dt + c4 * 4];
                cs[c4 * 4 + 0][r] = wv.x; cs[c4 * 4 + 1][r] = wv.y;
                cs[c4 * 4 + 2][r] = wv.z; cs[c4 * 4 + 3][r] = wv.w;
            }
            __syncthreads();

#pragma unroll 8
            for (int d = 0; d < BD; ++d) {
                u64 zap = *(const u64*)&zs[d][ty * 2];
#pragma unroll
                for (int j = 0; j < 8; ++j) {
                    float cc = cs[d][tx + 16 * j];
                    u64 cd;
                    DUP_F32X2(cd, __float_as_uint(cc));
                    FMA_F32X2(acc[j], zap, cd, acc[j]);
                }
            }
        }

#pragma unroll
        for (int j = 0; j < 8; ++j) {
            int kk = kt + tx + 16 * j;
            float cn = g_cnorm[kk];
            float a0 = lo32(acc[j]), a1 = hi32(acc[j]);
            float s0 = fmaf(-2.f, a0, zn_s[ty * 2 + 0]);
            float v0 = __fadd_rn(s0, cn);
            if (v0 < bestv[0]) { bestv[0] = v0; besti[0] = kk; }
            float s1 = fmaf(-2.f, a1, zn_s[ty * 2 + 1]);
            float v1 = __fadd_rn(s1, cn);
            if (v1 < bestv[1]) { bestv[1] = v1; besti[1] = kk; }
        }
    }

    __syncthreads();
#pragma unroll
    for (int i = 0; i < 2; ++i) {
        redv[ty * 2 + i][tx] = bestv[i];
        redi[ty * 2 + i][tx] = besti[i];
    }
    __syncthreads();
    if (tid < BM && blockRow + tid < nf) {
        float bv = redv[tid][0];
        int   bi = redi[tid][0];
#pragma unroll
        for (int t = 1; t < 16; ++t) {
            float v = redv[tid][t];
            int   ii = redi[tid][t];
            if (v < bv || (v == bv && ii < bi)) { bv = v; bi = ii; }
        }
        g_ids[ridx_s[tid]] = bi;
    }
}

// ---------------------------------------------------------------------------
// Outputs: z | z_q_st = z + (z_q - z) | ids | loss
// ---------------------------------------------------------------------------
__global__ void output_kernel(const float* __restrict__ z,
                              const float* __restrict__ cb,
                              float* __restrict__ out) {
    const size_t ND = (size_t)N_ROWS * DIM;
    int gtid = blockIdx.x * blockDim.x + threadIdx.x;
    size_t base = (size_t)gtid * 4;

    float local = 0.f;
    if (base < ND) {
        int n = (int)(base / DIM);
        int d = (int)(base % DIM);
        float4 zv = *(const float4*)&z[base];
        int id = g_ids[n];
        float4 cv = *(const float4*)&cb[(size_t)id * DIM + d];
        *(float4*)&out[base] = zv;
        float tx_ = __fadd_rn(cv.x, -zv.x), ty_ = __fadd_rn(cv.y, -zv.y);
        float tz_ = __fadd_rn(cv.z, -zv.z), tw_ = __fadd_rn(cv.w, -zv.w);
        float4 st;
        st.x = __fadd_rn(zv.x, tx_); st.y = __fadd_rn(zv.y, ty_);
        st.z = __fadd_rn(zv.z, tz_); st.w = __fadd_rn(zv.w, tw_);
        *(float4*)&out[ND + base] = st;
        local = tx_ * tx_ + ty_ * ty_ + tz_ * tz_ + tw_ * tw_;
    }
    if (gtid < N_ROWS) out[2 * ND + gtid] = (float)g_ids[gtid];

    __shared__ float warp_s[8];
#pragma unroll
    for (int o = 16; o > 0; o >>= 1)
        local += __shfl_down_sync(0xFFFFFFFFu, local, o);
    if ((threadIdx.x & 31) == 0) warp_s[threadIdx.x >> 5] = local;
    __syncthreads();
    if (threadIdx.x < 8) {
        float v = warp_s[threadIdx.x];
#pragma unroll
        for (int o = 4; o > 0; o >>= 1)
            v += __shfl_down_sync(0xFFu, v, o);
        if (threadIdx.x == 0 && v != 0.f) atomicAdd(&g_loss, (double)v);
    }
}

__global__ void finalize_kernel(float* __restrict__ out) {
    const size_t ND = (size_t)N_ROWS * DIM;
    out[2 * ND + N_ROWS] = (float)(1.25 * g_loss / (double)ND);
}

// ---------------------------------------------------------------------------
extern "C" void kernel_launch(void* const* d_in, const int* in_sizes, int n_in,
                              void* d_out, int out_size) {
    const float* z  = (const float*)d_in[0];
    const float* cb = (const float*)d_in[1];
    float* out = (float*)d_out;

    cudaFuncSetAttribute(screen_kernel, cudaFuncAttributeMaxDynamicSharedMemorySize, S_TOT);

    norms_kernel<<<(N_ROWS * 32 + 255) / 256, 256>>>(z, cb);
    screen_kernel<<<N_ROWS / 128, 128, S_TOT>>>();
    lite_kernel<<<296, 256>>>(z, cb);
    rescue_kernel<<<N_ROWS / BM, 256>>>(z, cb);
    const size_t ND = (size_t)N_ROWS * DIM;
    int nblk = (int)((ND / 4 + 255) / 256);
    output_kernel<<<nblk, 256>>>(z, cb, out);
    finalize_kernel<<<1, 1>>>(out);
}

// round 14
// speedup vs baseline: 1.6032x; 1.6032x over previous
#include <cuda_runtime.h>
#include <cuda_bf16.h>
#include <cstdint>

#define N_ROWS 131072
#define DIM    256
#define KCB    1024
#define DELTA  1.0e-3f

// full-rescue tile
#define BM 32
#define BN 128
#define BD 32
#define PAD 4

__device__ float  g_cnorm[KCB];
__device__ float  g_zn[N_ROWS];
__device__ int    g_ids[N_ROWS];
__device__ int    g_lite[N_ROWS];
__device__ int    g_c1[N_ROWS];
__device__ int    g_c2[N_ROWS];
__device__ int    g_full[N_ROWS];
__device__ unsigned long long g_best[N_ROWS];
__device__ int    g_nlite;
__device__ int    g_nfull;
__device__ double g_loss;
__device__ __align__(16) __nv_bfloat16 g_cbh[KCB * DIM];

typedef unsigned long long u64;

#define FMA_F32X2(d, a, b, c) \
    asm("fma.rn.f32x2 %0, %1, %2, %3;" : "=l"(d) : "l"(a), "l"(b), "l"(c))
#define DUP_F32X2(d, x) \
    asm("mov.b64 %0, {%1, %1};" : "=l"(d) : "r"(x))
__device__ __forceinline__ float lo32(u64 v) { return __uint_as_float((unsigned)(v & 0xFFFFFFFFu)); }
__device__ __forceinline__ float hi32(u64 v) { return __uint_as_float((unsigned)(v >> 32)); }

// monotone float->uint encoding: enc(a) < enc(b) iff a < b
__device__ __forceinline__ unsigned fenc(float v) {
    unsigned u = __float_as_uint(v);
    return (u & 0x80000000u) ? ~u : (u | 0x80000000u);
}

// ---------------------------------------------------------------------------
// Bit-exact row norms (XLA order) + codebook bf16 pre-conversion
// ---------------------------------------------------------------------------
__device__ __forceinline__ float row_sumsq_warp(const float* __restrict__ row, int lane) {
    float s = 0.f;
#pragma unroll
    for (int i = 0; i < DIM / 32; ++i) {
        float v = row[lane + i * 32];
        s = __fadd_rn(s, __fmul_rn(v, v));
    }
#pragma unroll
    for (int o = 16; o > 0; o >>= 1)
        s = __fadd_rn(s, __shfl_down_sync(0xFFFFFFFFu, s, o));
    return s;
}

__global__ void norms_kernel(const float* __restrict__ z, const float* __restrict__ cb) {
    int gtid = blockIdx.x * blockDim.x + threadIdx.x;
    int warp = gtid >> 5;
    int lane = threadIdx.x & 31;
    if (gtid == 0) { g_loss = 0.0; g_nlite = 0; g_nfull = 0; }
    if (gtid < KCB * DIM / 8) {
        const float4* p = (const float4*)&cb[(size_t)gtid * 8];
        float4 a = p[0], b = p[1];
        __nv_bfloat162 h0 = __floats2bfloat162_rn(a.x, a.y), h1 = __floats2bfloat162_rn(a.z, a.w);
        __nv_bfloat162 h2 = __floats2bfloat162_rn(b.x, b.y), h3 = __floats2bfloat162_rn(b.z, b.w);
        uint4 u;
        u.x = *(uint32_t*)&h0; u.y = *(uint32_t*)&h1;
        u.z = *(uint32_t*)&h2; u.w = *(uint32_t*)&h3;
        *(uint4*)&g_cbh[(size_t)gtid * 8] = u;
    }
    if (warp < N_ROWS) {
        float s = row_sumsq_warp(z + (size_t)warp * DIM, lane);
        if (lane == 0) g_zn[warp] = s;
    }
    if (warp < KCB) {
        float s = row_sumsq_warp(cb + (size_t)warp * DIM, lane);
        if (lane == 0) g_cnorm[warp] = s;
    }
}

// ---------------------------------------------------------------------------
// Screening: raw mma.sync.m16n8k16 bf16->fp32, top-3 per row, z pass-through.
// CTA = 256 threads (8 warps), 256 rows/CTA; cp.async double-buffered cb.
// ---------------------------------------------------------------------------
#define LDZ 264
#define S_Z    0                       // z bf16 [256][LDZ]   135168 B
#define S_CB0  135168                  // cb buf0 [64][LDZ]    33792 B
#define S_CB1  168960                  // cb buf1 [64][LDZ]    33792 B
#define S_CN   202752                  // cnorm f32 [1024]      4096 B
#define S_TOT  206848

#define LDSM_X4(r0, r1, r2, r3, addr) \
    asm volatile("ldmatrix.sync.aligned.m8n8.x4.shared.b16 {%0,%1,%2,%3}, [%4];" \
                 : "=r"(r0), "=r"(r1), "=r"(r2), "=r"(r3) : "r"(addr))
#define LDSM_X2(r0, r1, addr) \
    asm volatile("ldmatrix.sync.aligned.m8n8.x2.shared.b16 {%0,%1}, [%2];" \
                 : "=r"(r0), "=r"(r1) : "r"(addr))
#define MMA16816(c, a, b) \
    asm volatile("mma.sync.aligned.m16n8k16.row.col.f32.bf16.bf16.f32 " \
                 "{%0,%1,%2,%3}, {%4,%5,%6,%7}, {%8,%9}, {%0,%1,%2,%3};" \
                 : "+f"((c)[0]), "+f"((c)[1]), "+f"((c)[2]), "+f"((c)[3]) \
                 : "r"((a)[0]), "r"((a)[1]), "r"((a)[2]), "r"((a)[3]), \
                   "r"((b)[0]), "r"((b)[1]))
#define CP_ASYNC16(smem_addr, gptr) \
    asm volatile("cp.async.cg.shared.global [%0], [%1], 16;" \
                 :: "r"(smem_addr), "l"(gptr) : "memory")
#define CP_COMMIT() asm volatile("cp.async.commit_group;" ::: "memory")

__device__ __forceinline__ uint32_t smem_u32(const void* p) {
    uint32_t a;
    asm("{ .reg .u64 t; cvta.to.shared.u64 t, %1; cvt.u32.u64 %0, t; }" : "=r"(a) : "l"(p));
    return a;
}

__global__ void __launch_bounds__(256)
screen_kernel(const float* __restrict__ z, float* __restrict__ out) {
    extern __shared__ char smem[];
    __nv_bfloat16* zt = (__nv_bfloat16*)(smem + S_Z);
    float* cn_s = (float*)(smem + S_CN);

    const int tid = threadIdx.x, w = tid >> 5, lane = tid & 31;
    const int blockRow = blockIdx.x * 256;
    const int warpRow = w * 32;

    const uint32_t sb = smem_u32(smem);
    const uint32_t cbBuf[2] = {sb + S_CB0, sb + S_CB1};

    for (int t = tid; t < KCB; t += 256) cn_s[t] = g_cnorm[t];

    // stage z tile [256 x 256] f32 -> bf16 ; pass z through to out
    for (int t = tid; t < 256 * 32; t += 256) {
        int row = t >> 5, c8 = t & 31;
        size_t base = (size_t)(blockRow + row) * DIM + c8 * 8;
        const float4* p = (const float4*)&z[base];
        float4 a = p[0], b = p[1];
        *(float4*)&out[base] = a;
        *(float4*)&out[base + 4] = b;
        __nv_bfloat162 h0 = __floats2bfloat162_rn(a.x, a.y), h1 = __floats2bfloat162_rn(a.z, a.w);
        __nv_bfloat162 h2 = __floats2bfloat162_rn(b.x, b.y), h3 = __floats2bfloat162_rn(b.z, b.w);
        uint4 u;
        u.x = *(uint32_t*)&h0; u.y = *(uint32_t*)&h1;
        u.z = *(uint32_t*)&h2; u.w = *(uint32_t*)&h3;
        *(uint4*)&zt[row * LDZ + c8 * 8] = u;
    }

    auto stage = [&](int c, uint32_t buf) {
#pragma unroll
        for (int i = 0; i < 8; ++i) {
            int idx = tid + i * 256;         // 0..2047
            int row = idx >> 5;
            int c16 = idx & 31;
            const __nv_bfloat16* src = &g_cbh[(size_t)(c * 64 + row) * DIM + c16 * 8];
            uint32_t dst = buf + (uint32_t)(row * LDZ + c16 * 8) * 2;
            CP_ASYNC16(dst, src);
        }
        CP_COMMIT();
    };

    const int a_row = (lane & 7) + ((lane >> 3) & 1) * 8;
    const int a_col = ((lane >> 4) & 1) * 8;
    const uint32_t ztb = sb + S_Z;
    uint32_t addrA0 = ztb + ((warpRow + a_row) * LDZ + a_col) * 2;
    uint32_t addrA1 = ztb + ((warpRow + 16 + a_row) * LDZ + a_col) * 2;
    const int b_code = (lane & 7);
    const int b_koff = ((lane >> 3) & 1) * 8;

    // 4 row-slots: s = mt*2+hi -> row warpRow + mt*16 + (lane>>2) + hi*8
    float b1[4], b2[4], b3[4];
    int   i1[4], i2[4], i3[4];
#pragma unroll
    for (int s = 0; s < 4; ++s) {
        b1[s] = b2[s] = b3[s] = 3.4e38f;
        i1[s] = i2[s] = i3[s] = 0;
    }

    stage(0, cbBuf[0]);

#pragma unroll 1
    for (int c = 0; c < 16; ++c) {
        if (c < 15) { stage(c + 1, cbBuf[(c + 1) & 1]);
                      asm volatile("cp.async.wait_group 1;" ::: "memory"); }
        else        { asm volatile("cp.async.wait_group 0;" ::: "memory"); }
        __syncthreads();
        const uint32_t cbb = cbBuf[c & 1];

        float acc[2][8][4];
#pragma unroll
        for (int mt = 0; mt < 2; ++mt)
#pragma unroll
            for (int nt = 0; nt < 8; ++nt)
#pragma unroll
                for (int e = 0; e < 4; ++e) acc[mt][nt][e] = 0.f;

#pragma unroll
        for (int ks = 0; ks < 16; ++ks) {
            uint32_t a0[4], a1[4];
            LDSM_X4(a0[0], a0[1], a0[2], a0[3], addrA0 + ks * 32);
            LDSM_X4(a1[0], a1[1], a1[2], a1[3], addrA1 + ks * 32);
            uint32_t bf[8][2];
#pragma unroll
            for (int nt = 0; nt < 8; ++nt) {
                uint32_t ab = cbb + ((nt * 8 + b_code) * LDZ + b_koff + ks * 16) * 2;
                LDSM_X2(bf[nt][0], bf[nt][1], ab);
            }
#pragma unroll
            for (int nt = 0; nt < 8; ++nt) {
                MMA16816(acc[0][nt], a0, bf[nt]);
                MMA16816(acc[1][nt], a1, bf[nt]);
            }
        }

        const int kq = 2 * (lane & 3);
#pragma unroll
        for (int nt = 0; nt < 8; ++nt) {
            int k0 = c * 64 + nt * 8 + kq;
            float cn0 = cn_s[k0], cn1 = cn_s[k0 + 1];
#pragma unroll
            for (int mt = 0; mt < 2; ++mt) {
#pragma unroll
                for (int hi = 0; hi < 2; ++hi) {
                    int s = mt * 2 + hi;
                    float d0 = acc[mt][nt][hi * 2 + 0];
                    float d1 = acc[mt][nt][hi * 2 + 1];
                    float v0 = fmaf(-2.f, d0, cn0);
                    float v1 = fmaf(-2.f, d1, cn1);
                    if (v0 < b1[s]) { b3[s]=b2[s]; i3[s]=i2[s]; b2[s]=b1[s]; i2[s]=i1[s]; b1[s]=v0; i1[s]=k0; }
                    else if (v0 < b2[s]) { b3[s]=b2[s]; i3[s]=i2[s]; b2[s]=v0; i2[s]=k0; }
                    else if (v0 < b3[s]) { b3[s]=v0; i3[s]=k0; }
                    if (v1 < b1[s]) { b3[s]=b2[s]; i3[s]=i2[s]; b2[s]=b1[s]; i2[s]=i1[s]; b1[s]=v1; i1[s]=k0+1; }
                    else if (v1 < b2[s]) { b3[s]=b2[s]; i3[s]=i2[s]; b2[s]=v1; i2[s]=k0+1; }
                    else if (v1 < b3[s]) { b3[s]=v1; i3[s]=k0+1; }
                }
            }
        }
        __syncthreads();
    }

    // quad merge of top-3
#pragma unroll
    for (int off = 1; off <= 2; off <<= 1) {
#pragma unroll
        for (int s = 0; s < 4; ++s) {
            float o1 = __shfl_xor_sync(0xFFFFFFFFu, b1[s], off);
            float o2 = __shfl_xor_sync(0xFFFFFFFFu, b2[s], off);
            float o3 = __shfl_xor_sync(0xFFFFFFFFu, b3[s], off);
            int   j1 = __shfl_xor_sync(0xFFFFFFFFu, i1[s], off);
            int   j2 = __shfl_xor_sync(0xFFFFFFFFu, i2[s], off);
            int   j3 = __shfl_xor_sync(0xFFFFFFFFu, i3[s], off);
#pragma unroll
            for (int t = 0; t < 3; ++t) {
                float ov = (t == 0) ? o1 : (t == 1) ? o2 : o3;
                int   oj = (t == 0) ? j1 : (t == 1) ? j2 : j3;
                if (ov < b1[s]) { b3[s]=b2[s]; i3[s]=i2[s]; b2[s]=b1[s]; i2[s]=i1[s]; b1[s]=ov; i1[s]=oj; }
                else if (ov < b2[s]) { b3[s]=b2[s]; i3[s]=i2[s]; b2[s]=ov; i2[s]=oj; }
                else if (ov < b3[s]) { b3[s]=ov; i3[s]=oj; }
            }
        }
    }

    if ((lane & 3) == 0) {
#pragma unroll
        for (int s = 0; s < 4; ++s) {
            int row = blockRow + warpRow + (s >> 1) * 16 + (lane >> 2) + (s & 1) * 8;
            g_ids[row] = i1[s];
            if (b2[s] - b1[s] < DELTA) {
                if (b3[s] - b1[s] < DELTA) {
                    g_best[row] = 0xFFFFFFFFFFFFFFFFull;
                    int p = atomicAdd(&g_nfull, 1);
                    g_full[p] = row;
                } else {
                    int p = atomicAdd(&g_nlite, 1);
                    g_lite[p] = row; g_c1[p] = i1[s]; g_c2[p] = i2[s];
                }
            }
        }
    }
}

// ---------------------------------------------------------------------------
// Lite rescue: exact quantized 2-candidate compare (bit-exact serial chains)
// ---------------------------------------------------------------------------
__global__ void __launch_bounds__(256)
lite_kernel(const float* __restrict__ z, const float* __restrict__ cb) {
    __shared__ float buf[8][3][DIM];
    const int lw = threadIdx.x >> 5, lane = threadIdx.x & 31;
    const int nwarps = gridDim.x * 8;
    const int nl = g_nlite;
    for (int wi = blockIdx.x * 8 + lw; wi < nl; wi += nwarps) {
        int row = g_lite[wi], c1 = g_c1[wi], c2 = g_c2[wi];
        {
            const float4* pz = (const float4*)(z + (size_t)row * DIM);
            const float4* p1 = (const float4*)(cb + (size_t)c1 * DIM);
            const float4* p2 = (const float4*)(cb + (size_t)c2 * DIM);
            float4* bz = (float4*)buf[lw][0];
            float4* b1 = (float4*)buf[lw][1];
            float4* b2 = (float4*)buf[lw][2];
            bz[lane] = pz[lane]; bz[lane + 32] = pz[lane + 32];
            b1[lane] = p1[lane]; b1[lane + 32] = p1[lane + 32];
            b2[lane] = p2[lane]; b2[lane + 32] = p2[lane + 32];
        }
        __syncwarp();
        if (lane == 0) {
            float e1 = 0.f, e2 = 0.f;
#pragma unroll 16
            for (int d = 0; d < DIM; ++d) {
                float zv = buf[lw][0][d];
                e1 = fmaf(zv, buf[lw][1][d], e1);
                e2 = fmaf(zv, buf[lw][2][d], e2);
            }
            float zn = g_zn[row];
            float v1 = __fadd_rn(fmaf(-2.f, e1, zn), g_cnorm[c1]);
            float v2 = __fadd_rn(fmaf(-2.f, e2, zn), g_cnorm[c2]);
            int id = c1;
            if (v2 < v1 || (v2 == v1 && c2 < c1)) id = c2;
            g_ids[row] = id;
        }
        __syncwarp();
    }
}

// ---------------------------------------------------------------------------
// Full rescue, k-sliced 8x: block (rb, slice) does 32 rows x 128 codes exact,
// merges via atomicMin on (enc(score)<<32 | idx) -- exact reference argmin
// order (min value, lowest index) independent of block ordering.
// ---------------------------------------------------------------------------
__global__ void __launch_bounds__(256)
rescue_kernel(const float* __restrict__ z, const float* __restrict__ cb) {
    __shared__ __align__(16) float zs[BD][BM + PAD];
    __shared__ __align__(16) float cs[BD][BN + PAD];
    __shared__ float zn_s[BM];
    __shared__ int   ridx_s[BM];
    __shared__ float redv[BM][16];
    __shared__ int   redi[BM][16];

    const int nf = g_nfull;
    const int slice = blockIdx.x & 7;
    const int rbStride = gridDim.x >> 3;
    const int kt = slice * BN;

    const int tid = threadIdx.x;
    const int tx = tid & 15;
    const int ty = tid >> 4;
    const int c4 = tid & 7;
    const int r0 = tid >> 3;

    for (int rb = blockIdx.x >> 3; rb * BM < nf; rb += rbStride) {
        const int blockRow = rb * BM;
        __syncthreads();
        if (tid < BM) {
            int s = blockRow + tid;
            int r = g_full[(s < nf) ? s : blockRow];
            ridx_s[tid] = r;
            zn_s[tid] = g_zn[r];
        }

        float bestv[2] = {3.4e38f, 3.4e38f};
        int   besti[2] = {0, 0};

        u64 acc[8];
#pragma unroll
        for (int j = 0; j < 8; ++j) acc[j] = 0ull;

#pragma unroll 1
        for (int dt = 0; dt < DIM; dt += BD) {
            __syncthreads();
            if (r0 < 32) {
                float4 v = *(const float4*)&z[(size_t)ridx_s[r0] * DIM + dt + c4 * 4];
                zs[c4 * 4 + 0][r0] = v.x; zs[c4 * 4 + 1][r0] = v.y;
                zs[c4 * 4 + 2][r0] = v.z; zs[c4 * 4 + 3][r0] = v.w;
            }
#pragma unroll
            for (int q = 0; q < 4; ++q) {
                int r = q * 32 + r0;
                float4 wv = *(const float4*)&cb[(size_t)(kt + r) * DIM + dt + c4 * 4];
                cs[c4 * 4 + 0][r] = wv.x; cs[c4 * 4 + 1][r] = wv.y;
                cs[c4 * 4 + 2][r] = wv.z; cs[c4 * 4 + 3][r] = wv.w;
            }
            __syncthreads();

#pragma unroll 8
            for (int d = 0; d < BD; ++d) {
                u64 zap = *(const u64*)&zs[d][ty * 2];
#pragma unroll
                for (int j = 0; j < 8; ++j) {
                    float cc = cs[d][tx + 16 * j];
                    u64 cd;
                    DUP_F32X2(cd, __float_as_uint(cc));
                    FMA_F32X2(acc[j], zap, cd, acc[j]);
                }
            }
        }

#pragma unroll
        for (int j = 0; j < 8; ++j) {
            int kk = kt + tx + 16 * j;
            float cn = g_cnorm[kk];
            float a0 = lo32(acc[j]), a1 = hi32(acc[j]);
            float s0 = fmaf(-2.f, a0, zn_s[ty * 2 + 0]);
            float v0 = __fadd_rn(s0, cn);
            if (v0 < bestv[0]) { bestv[0] = v0; besti[0] = kk; }
            float s1 = fmaf(-2.f, a1, zn_s[ty * 2 + 1]);
            float v1 = __fadd_rn(s1, cn);
            if (v1 < bestv[1]) { bestv[1] = v1; besti[1] = kk; }
        }

        __syncthreads();
#pragma unroll
        for (int i = 0; i < 2; ++i) {
            redv[ty * 2 + i][tx] = bestv[i];
            redi[ty * 2 + i][tx] = besti[i];
        }
        __syncthreads();
        if (tid < BM && blockRow + tid < nf) {
            float bv = redv[tid][0];
            int   bi = redi[tid][0];
#pragma unroll
            for (int t = 1; t < 16; ++t) {
                float v = redv[tid][t];
                int   ii = redi[tid][t];
                if (v < bv || (v == bv && ii < bi)) { bv = v; bi = ii; }
            }
            u64 pk = ((u64)fenc(bv) << 32) | (unsigned)bi;
            atomicMin(&g_best[ridx_s[tid]], pk);
        }
    }
}

__global__ void fixup_kernel() {
    int nf = g_nfull;
    for (int i = blockIdx.x * blockDim.x + threadIdx.x; i < nf; i += gridDim.x * blockDim.x) {
        int row = g_full[i];
        g_ids[row] = (int)(g_best[row] & 0xFFFFFFFFull);
    }
}

// ---------------------------------------------------------------------------
// Outputs: z_q_st = z + (z_q - z) | ids | loss   (z section written by screen)
// ---------------------------------------------------------------------------
__global__ void output_kernel(const float* __restrict__ z,
                              const float* __restrict__ cb,
                              float* __restrict__ out) {
    const size_t ND = (size_t)N_ROWS * DIM;
    int gtid = blockIdx.x * blockDim.x + threadIdx.x;
    size_t base = (size_t)gtid * 4;

    float local = 0.f;
    if (base < ND) {
        int n = (int)(base / DIM);
        int d = (int)(base % DIM);
        float4 zv = *(const float4*)&z[base];
        int id = g_ids[n];
        float4 cv = *(const float4*)&cb[(size_t)id * DIM + d];
        float tx_ = __fadd_rn(cv.x, -zv.x), ty_ = __fadd_rn(cv.y, -zv.y);
        float tz_ = __fadd_rn(cv.z, -zv.z), tw_ = __fadd_rn(cv.w, -zv.w);
        float4 st;
        st.x = __fadd_rn(zv.x, tx_); st.y = __fadd_rn(zv.y, ty_);
        st.z = __fadd_rn(zv.z, tz_); st.w = __fadd_rn(zv.w, tw_);
        *(float4*)&out[ND + base] = st;
        local = tx_ * tx_ + ty_ * ty_ + tz_ * tz_ + tw_ * tw_;
    }
    if (gtid < N_ROWS) out[2 * ND + gtid] = (float)g_ids[gtid];

    __shared__ float warp_s[8];
#pragma unroll
    for (int o = 16; o > 0; o >>= 1)
        local += __shfl_down_sync(0xFFFFFFFFu, local, o);
    if ((threadIdx.x & 31) == 0) warp_s[threadIdx.x >> 5] = local;
    __syncthreads();
    if (threadIdx.x < 8) {
        float v = warp_s[threadIdx.x];
#pragma unroll
        for (int o = 4; o > 0; o >>= 1)
            v += __shfl_down_sync(0xFFu, v, o);
        if (threadIdx.x == 0 && v != 0.f) atomicAdd(&g_loss, (double)v);
    }
}

__global__ void finalize_kernel(float* __restrict__ out) {
    const size_t ND = (size_t)N_ROWS * DIM;
    out[2 * ND + N_ROWS] = (float)(1.25 * g_loss / (double)ND);
}

// ---------------------------------------------------------------------------
extern "C" void kernel_launch(void* const* d_in, const int* in_sizes, int n_in,
                              void* d_out, int out_size) {
    const float* z  = (const float*)d_in[0];
    const float* cb = (const float*)d_in[1];
    float* out = (float*)d_out;

    cudaFuncSetAttribute(screen_kernel, cudaFuncAttributeMaxDynamicSharedMemorySize, S_TOT);

    norms_kernel<<<(N_ROWS * 32 + 255) / 256, 256>>>(z, cb);
    screen_kernel<<<N_ROWS / 256, 256, S_TOT>>>(z, out);
    lite_kernel<<<296, 256>>>(z, cb);
    rescue_kernel<<<1184, 256>>>(z, cb);
    fixup_kernel<<<32, 256>>>();
    const size_t ND = (size_t)N_ROWS * DIM;
    int nblk = (int)((ND / 4 + 255) / 256);
    output_kernel<<<nblk, 256>>>(z, cb, out);
    finalize_kernel<<<1, 1>>>(out);
}